// round 5
// baseline (speedup 1.0000x reference)
#include <cuda_runtime.h>
#include <cuda_bf16.h>

// Problem constants
#define VD 128
#define VH 128
#define VW 128
#define VOL (VD*VH*VW)     // 2097152
#define NP 4
#define RD 192
#define RH 192
#define NW 128
#define NPIX (NP*RD*RH)    // 147456 per batch
#define BATCH 2
#define OH 256
#define OW 256
#define NQ 4               // ray quarters
#define WQ (NW/NQ)         // 32 w-steps per block

typedef unsigned long long u64;

// Scratch
__device__ float4 g_vol4[VOL];            // {b0[i], b1[i], b0[i+1], b1[i+1]} (32 MB)
__device__ float4 g_xprojP[NPIX * BATCH]; // [pix][b] -> 4 quarter partials
__device__ float  g_tabIx[NP * NW * RH];  // pre-scaled ix, [p][w][rh]
__device__ float  g_tabD [NP * RD * NW];  // c2 table, [p][rd][w]
__device__ float  g_tabH [NW];            // c1 table, [w]

__device__ __forceinline__ int clampi(int v, int lo, int hi) {
    return v < lo ? lo : (v > hi ? hi : v);
}

// ---- f32x2 packed helpers (sm_103a) ----
__device__ __forceinline__ u64 fma2(u64 a, u64 b, u64 c) {
    u64 d; asm("fma.rn.f32x2 %0, %1, %2, %3;" : "=l"(d) : "l"(a), "l"(b), "l"(c)); return d;
}
__device__ __forceinline__ u64 mul2(u64 a, u64 b) {
    u64 d; asm("mul.rn.f32x2 %0, %1, %2;" : "=l"(d) : "l"(a), "l"(b)); return d;
}
__device__ __forceinline__ u64 pack2(float lo, float hi) {
    u64 d; asm("mov.b64 %0, {%1, %2};" : "=l"(d) : "f"(lo), "f"(hi)); return d;
}
__device__ __forceinline__ float2 unpack2(u64 v) {
    float lo, hi; asm("mov.b64 {%0, %1}, %2;" : "=f"(lo), "=f"(hi) : "l"(v));
    return make_float2(lo, hi);
}

// ---------------------------------------------------------------------------
// Fused prep: vectorized pair-pack (blocks 0..2047) + table extraction.
// ---------------------------------------------------------------------------
#define PACK_BLOCKS (VOL/4/256)    // 2048 (each thread emits 4 float4s)
__global__ __launch_bounds__(256)
void prep_kernel(const float* __restrict__ x, const float* __restrict__ grids)
{
    if (blockIdx.x < PACK_BLOCKS) {
        const int t = blockIdx.x * 256 + threadIdx.x;   // 0..VOL/4-1
        const float4* __restrict__ x4 = (const float4*)x;
        const float4 a = __ldg(&x4[t]);                 // b0: i..i+3
        const float4 b = __ldg(&x4[t + VOL/4]);         // b1: i..i+3
        int i4 = 4 * t + 4; if (i4 > VOL - 1) i4 = VOL - 1;  // clamped (value unused)
        const float a4 = __ldg(&x[i4]);
        const float b4 = __ldg(&x[i4 + VOL]);
        const int base = 4 * t;
        g_vol4[base + 0] = make_float4(a.x, b.x, a.y, b.y);
        g_vol4[base + 1] = make_float4(a.y, b.y, a.z, b.z);
        g_vol4[base + 2] = make_float4(a.z, b.z, a.w, b.w);
        g_vol4[base + 3] = make_float4(a.w, b.w, a4, b4);
        return;
    }
    const int tid = (blockIdx.x - PACK_BLOCKS) * 256 + threadIdx.x;
    const int NA = NP * NW * RH;   // 98304
    const int NB = NP * RD * NW;   // 98304
    if (tid < NA) {
        int rh = tid % RH;
        int pw = tid / RH;
        int w  = pw % NW;
        int p  = pw / NW;
        const float c0 = __ldg(&grids[(((size_t)(p * RD + 0) * RH + rh) * NW + w) * 3 + 0]);
        g_tabIx[tid] = (c0 + 1.0f) * (0.5f * (VW - 1));   // store ix directly
    } else if (tid < NA + NB) {
        int t = tid - NA;
        g_tabD[t] = __ldg(&grids[(((size_t)(t / NW) * RH + 0) * NW + (t % NW)) * 3 + 2]);
    } else if (tid < NA + NB + NW) {
        int w = tid - NA - NB;
        g_tabH[w] = __ldg(&grids[(size_t)w * 3 + 1]);
    }
}

// ---------------------------------------------------------------------------
// Projection: block = (p, rd-pair, quarter); 384 threads = 2 rd x 192 rh.
// Per (z,y) tap-row: LDS.128 {row, wk2} + LDG.128 {both taps, both batches}
// + 3 f32x2 ops. Adjacent rd share ~2/3 of volume rows -> L1 reuse.
// ---------------------------------------------------------------------------
__global__ __launch_bounds__(384)
void proj5_kernel(const float* __restrict__ dx)
{
    const int bid  = blockIdx.x;        // 0..1535
    const int q    = bid & (NQ - 1);
    const int blk2 = bid >> 2;          // p*(RD/2) + rd/2
    const int p    = blk2 / (RD / 2);
    const int rd0  = (blk2 % (RD / 2)) * 2;
    const int rdl  = threadIdx.x / RH;  // 0 or 1
    const int rh   = threadIdx.x % RH;
    const int W0   = q * WQ;

    __shared__ ulonglong2 s_rw[2][4][WQ];   // {.x = row base, .y = {wk,wk}}

    if (threadIdx.x < 2 * WQ) {
        const int rl = threadIdx.x >> 5;        // which rd of the pair
        const int wi = threadIdx.x & 31;
        const int w  = W0 + wi;
        const int blk = p * RD + rd0 + rl;
        const float c1 = g_tabH[w];
        const float c2 = g_tabD[blk * NW + w];
        const float iy = (c1 + 1.0f) * (0.5f * (VH - 1));
        const float iz = (c2 + 1.0f) * (0.5f * (VD - 1));
        const float y0f = floorf(iy);
        const float z0f = floorf(iz);
        const float fy = iy - y0f;
        const float fz = iz - z0f;
        const int y0 = (int)y0f;
        const int z0 = (int)z0f;

        float wy0 = (y0 >= 0     && y0     <= VH - 1) ? (1.0f - fy) : 0.0f;
        float wy1 = (y0 + 1 >= 0 && y0 + 1 <= VH - 1) ? fy : 0.0f;
        float wz0 = (z0 >= 0     && z0     <= VD - 1) ? (1.0f - fz) : 0.0f;
        float wz1 = (z0 + 1 >= 0 && z0 + 1 <= VD - 1) ? fz : 0.0f;

        const int yc0 = clampi(y0,     0, VH - 1);
        const int yc1 = clampi(y0 + 1, 0, VH - 1);
        const int zc0 = clampi(z0,     0, VD - 1);
        const int zc1 = clampi(z0 + 1, 0, VD - 1);

        const float w00 = wz0 * wy0, w01 = wz0 * wy1;
        const float w10 = wz1 * wy0, w11 = wz1 * wy1;

        s_rw[rl][0][wi] = make_ulonglong2((unsigned)((zc0 * VH + yc0) * VW), pack2(w00, w00));
        s_rw[rl][1][wi] = make_ulonglong2((unsigned)((zc0 * VH + yc1) * VW), pack2(w01, w01));
        s_rw[rl][2][wi] = make_ulonglong2((unsigned)((zc1 * VH + yc0) * VW), pack2(w10, w10));
        s_rw[rl][3][wi] = make_ulonglong2((unsigned)((zc1 * VH + yc1) * VW), pack2(w11, w11));
    }
    __syncthreads();

    const float* __restrict__ tIx = g_tabIx + (size_t)p * NW * RH + rh;
    const ulonglong2* __restrict__ vol = (const ulonglong2*)g_vol4;

    u64 acc = 0;   // packed {s_batch0, s_batch1} (bits of {0.f,0.f})

    #pragma unroll 8
    for (int i = 0; i < WQ; ++i) {
        const int w = W0 + i;
        const float ix = __ldg(&tIx[(size_t)w * RH]);        // coalesced
        const int x0 = __float2int_rd(ix);
        const float fx = ix - (float)x0;

        const float wx0 = (x0 >= 0  && x0 <= VW - 1) ? (1.0f - fx) : 0.0f;
        const float wx1 = (x0 >= -1 && x0 <= VW - 2) ? fx : 0.0f;
        float w0, w1; int e;
        if (x0 < 0)            { w0 = wx1; w1 = 0.0f; e = 0; }        // tap at v[0]
        else if (x0 > VW - 2)  { w0 = 0.0f; w1 = wx0; e = VW - 2; }   // tap at v[127]
        else                   { w0 = wx0; w1 = wx1; e = x0; }

        const u64 w0d = pack2(w0, w0);
        const u64 w1d = pack2(w1, w1);

        #pragma unroll
        for (int k = 0; k < 4; ++k) {
            const ulonglong2 rw = s_rw[rdl][k][i];           // LDS.128 broadcast
            const ulonglong2 v  = __ldg(&vol[(int)rw.x + e]);// LDG.128: taps x batches
            acc = fma2(rw.y, fma2(v.y, w1d, mul2(v.x, w0d)), acc);
        }
    }

    const float2 s = unpack2(acc);
    const int pix = (p * RD + rd0 + rdl) * RH + rh;
    const float d = __ldg(&dx[pix]);
    ((float*)&g_xprojP[(size_t)pix * BATCH + 0])[q] = s.x * d;
    ((float*)&g_xprojP[(size_t)pix * BATCH + 1])[q] = s.y * d;
}

// ---------------------------------------------------------------------------
// Nearest resize (192,192)->(256,256), summing the 4 quarter partials.
// ---------------------------------------------------------------------------
__global__ __launch_bounds__(256)
void resize_kernel(float* __restrict__ out)
{
    const int tid = blockIdx.x * blockDim.x + threadIdx.x;
    if (tid >= BATCH * NP * OH * OW) return;
    const int ow = tid & (OW - 1);
    const int oh = (tid >> 8) & (OH - 1);
    const int c  = tid >> 16;             // c = b*NP + p
    const int b  = c >> 2;
    const int p  = c & 3;
    const int hi = (oh * 3) >> 2;
    const int wi = (ow * 3) >> 2;
    const size_t pix = (size_t)(p * RD + hi) * RH + wi;
    const float4 v = __ldg(&g_xprojP[pix * BATCH + b]);
    out[tid] = (v.x + v.y) + (v.z + v.w);
}

extern "C" void kernel_launch(void* const* d_in, const int* in_sizes, int n_in,
                              void* d_out, int out_size)
{
    const float* x     = (const float*)d_in[0];
    const float* grids = (const float*)d_in[1];
    const float* dx    = (const float*)d_in[2];
    float* out = (float*)d_out;

    const int n_ext = NP * NW * RH + NP * RD * NW + NW;            // 196736
    const int prep_blocks = PACK_BLOCKS + (n_ext + 255) / 256;     // 2048 + 769
    prep_kernel<<<prep_blocks, 256>>>(x, grids);

    proj5_kernel<<<NP * (RD / 2) * NQ, 384>>>(dx);                 // 1536 blocks

    const int total = BATCH * NP * OH * OW;
    resize_kernel<<<(total + 255) / 256, 256>>>(out);
}

// round 6
// speedup vs baseline: 1.1500x; 1.1500x over previous
#include <cuda_runtime.h>
#include <cuda_fp16.h>
#include <cuda_bf16.h>

// Problem constants
#define VD 128
#define VH 128
#define VW 128
#define VOL (VD*VH*VW)     // 2097152
#define NP 4
#define RD 192
#define RH 192
#define NW 128
#define NPIX (NP*RD*RH)    // 147456 per batch
#define BATCH 2
#define OH 256
#define OW 256
#define NQ 4               // ray quarters
#define WQ (NW/NQ)         // 32 w-steps per block

typedef unsigned long long u64;

// Scratch
__device__ uint2  g_volh[VOL];            // {h2(b0[i],b1[i]), h2(b0[i+1],b1[i+1])} (16 MB)
__device__ float4 g_xprojP[NPIX * BATCH]; // [pix][b] -> 4 quarter partials
__device__ float  g_tabIx[NP * NW * RH];  // pre-scaled ix, [p][w][rh]
__device__ float  g_tabD [NP * RD * NW];  // c2 table, [p][rd][w]
__device__ float  g_tabH [NW];            // c1 table, [w]

__device__ __forceinline__ int clampi(int v, int lo, int hi) {
    return v < lo ? lo : (v > hi ? hi : v);
}

// ---- f32x2 packed helpers (sm_103a) ----
__device__ __forceinline__ u64 fma2(u64 a, u64 b, u64 c) {
    u64 d; asm("fma.rn.f32x2 %0, %1, %2, %3;" : "=l"(d) : "l"(a), "l"(b), "l"(c)); return d;
}
__device__ __forceinline__ u64 mul2(u64 a, u64 b) {
    u64 d; asm("mul.rn.f32x2 %0, %1, %2;" : "=l"(d) : "l"(a), "l"(b)); return d;
}
__device__ __forceinline__ u64 pack2(float lo, float hi) {
    u64 d; asm("mov.b64 %0, {%1, %2};" : "=l"(d) : "f"(lo), "f"(hi)); return d;
}
__device__ __forceinline__ float2 unpack2(u64 v) {
    float lo, hi; asm("mov.b64 {%0, %1}, %2;" : "=f"(lo), "=f"(hi) : "l"(v));
    return make_float2(lo, hi);
}
__device__ __forceinline__ u64 h2_to_f32x2(unsigned h) {
    // half2 {lo,hi} -> packed f32x2 {lo,hi}
    __half2 hh = *reinterpret_cast<__half2*>(&h);
    float2 f = __half22float2(hh);
    return pack2(f.x, f.y);
}

// ---------------------------------------------------------------------------
// Fused prep: fp16 pair-pack (per-voxel threads, perfectly coalesced 8B
// stores — R5's per-thread-vectorized stores quadrupled store wavefronts)
// + separable-table extraction.
// ---------------------------------------------------------------------------
#define PACK_BLOCKS (VOL/256)      // 8192
__global__ __launch_bounds__(256)
void prep_kernel(const float* __restrict__ x, const float* __restrict__ grids)
{
    if (blockIdx.x < PACK_BLOCKS) {
        const int i   = blockIdx.x * 256 + threadIdx.x;
        const int ip1 = (i + 1 < VOL) ? i + 1 : i;   // clamped; unused at row end
        const float a0 = __ldg(&x[i]);
        const float a1 = __ldg(&x[ip1]);
        const float b0 = __ldg(&x[i + VOL]);
        const float b1 = __ldg(&x[ip1 + VOL]);
        const __half2 lo = __floats2half2_rn(a0, b0);   // {batch0, batch1} @ voxel i
        const __half2 hi = __floats2half2_rn(a1, b1);   // {batch0, batch1} @ voxel i+1
        g_volh[i] = make_uint2(*reinterpret_cast<const unsigned*>(&lo),
                               *reinterpret_cast<const unsigned*>(&hi));
        return;
    }
    const int tid = (blockIdx.x - PACK_BLOCKS) * 256 + threadIdx.x;
    const int NA = NP * NW * RH;   // 98304
    const int NB = NP * RD * NW;   // 98304
    if (tid < NA) {
        int rh = tid % RH;
        int pw = tid / RH;
        int w  = pw % NW;
        int p  = pw / NW;
        const float c0 = __ldg(&grids[(((size_t)(p * RD + 0) * RH + rh) * NW + w) * 3 + 0]);
        g_tabIx[tid] = (c0 + 1.0f) * (0.5f * (VW - 1));   // store ix directly
    } else if (tid < NA + NB) {
        int t = tid - NA;
        g_tabD[t] = __ldg(&grids[(((size_t)(t / NW) * RH + 0) * NW + (t % NW)) * 3 + 2]);
    } else if (tid < NA + NB + NW) {
        int w = tid - NA - NB;
        g_tabH[w] = __ldg(&grids[(size_t)w * 3 + 1]);
    }
}

// ---------------------------------------------------------------------------
// Projection: block = (p*RD+rd)*NQ + q; 192 threads = rh line; WQ w-steps.
// One LDG.64 per (z,y) row fetches both x-taps for both batches (fp16),
// interpolation in packed f32x2. Structure identical to R4's proj4.
// ---------------------------------------------------------------------------
__global__ __launch_bounds__(192)
void proj6_kernel(const float* __restrict__ dx)
{
    const int bid = blockIdx.x;
    const int q   = bid & (NQ - 1);
    const int blk = bid >> 2;          // p*RD + rd
    const int p   = blk / RD;
    const int rh  = threadIdx.x;
    const int W0  = q * WQ;

    __shared__ ulonglong2 s_rw[4][WQ];     // {.x = row base, .y = {wk,wk} f32x2}

    if (threadIdx.x < WQ) {
        const int w = W0 + threadIdx.x;
        const float c1 = g_tabH[w];
        const float c2 = g_tabD[blk * NW + w];
        const float iy = (c1 + 1.0f) * (0.5f * (VH - 1));
        const float iz = (c2 + 1.0f) * (0.5f * (VD - 1));
        const float y0f = floorf(iy);
        const float z0f = floorf(iz);
        const float fy = iy - y0f;
        const float fz = iz - z0f;
        const int y0 = (int)y0f;
        const int z0 = (int)z0f;

        float wy0 = (y0 >= 0     && y0     <= VH - 1) ? (1.0f - fy) : 0.0f;
        float wy1 = (y0 + 1 >= 0 && y0 + 1 <= VH - 1) ? fy : 0.0f;
        float wz0 = (z0 >= 0     && z0     <= VD - 1) ? (1.0f - fz) : 0.0f;
        float wz1 = (z0 + 1 >= 0 && z0 + 1 <= VD - 1) ? fz : 0.0f;

        const int yc0 = clampi(y0,     0, VH - 1);
        const int yc1 = clampi(y0 + 1, 0, VH - 1);
        const int zc0 = clampi(z0,     0, VD - 1);
        const int zc1 = clampi(z0 + 1, 0, VD - 1);

        const float w00 = wz0 * wy0, w01 = wz0 * wy1;
        const float w10 = wz1 * wy0, w11 = wz1 * wy1;

        s_rw[0][threadIdx.x] = make_ulonglong2((u64)((zc0 * VH + yc0) * VW), pack2(w00, w00));
        s_rw[1][threadIdx.x] = make_ulonglong2((u64)((zc0 * VH + yc1) * VW), pack2(w01, w01));
        s_rw[2][threadIdx.x] = make_ulonglong2((u64)((zc1 * VH + yc0) * VW), pack2(w10, w10));
        s_rw[3][threadIdx.x] = make_ulonglong2((u64)((zc1 * VH + yc1) * VW), pack2(w11, w11));
    }
    __syncthreads();

    const float* __restrict__ tIx = g_tabIx + (size_t)p * NW * RH + rh;

    u64 acc = 0;   // packed f32x2 {s_batch0, s_batch1}

    #pragma unroll 4
    for (int i = 0; i < WQ; ++i) {
        const int w = W0 + i;
        const float ix = __ldg(&tIx[(size_t)w * RH]);        // coalesced
        const int x0 = __float2int_rd(ix);
        const float fx = ix - (float)x0;

        // Tap weights, edge-remapped onto the pair {v[e], v[e+1]}, e=clamp(x0,0,126).
        const float wx0 = (x0 >= 0  && x0 <= VW - 1) ? (1.0f - fx) : 0.0f;
        const float wx1 = (x0 >= -1 && x0 <= VW - 2) ? fx : 0.0f;
        float w0, w1; int e;
        if (x0 < 0)            { w0 = wx1; w1 = 0.0f; e = 0; }        // tap at v[0]
        else if (x0 > VW - 2)  { w0 = 0.0f; w1 = wx0; e = VW - 2; }   // tap at v[127]
        else                   { w0 = wx0; w1 = wx1; e = x0; }

        const u64 w0d = pack2(w0, w0);
        const u64 w1d = pack2(w1, w1);

        #pragma unroll
        for (int k = 0; k < 4; ++k) {
            const ulonglong2 rw = s_rw[k][i];                // LDS.128 broadcast
            const uint2 v = __ldg(&g_volh[(int)rw.x + e]);   // LDG.64: taps x batches
            const u64 v0 = h2_to_f32x2(v.x);                 // {b0[e],   b1[e]}
            const u64 v1 = h2_to_f32x2(v.y);                 // {b0[e+1], b1[e+1]}
            acc = fma2(rw.y, fma2(v1, w1d, mul2(v0, w0d)), acc);
        }
    }

    const float2 s = unpack2(acc);
    const int pix = blk * RH + rh;
    const float d = __ldg(&dx[pix]);
    ((float*)&g_xprojP[(size_t)pix * BATCH + 0])[q] = s.x * d;
    ((float*)&g_xprojP[(size_t)pix * BATCH + 1])[q] = s.y * d;
}

// ---------------------------------------------------------------------------
// Nearest resize (192,192)->(256,256), summing the 4 quarter partials.
// ---------------------------------------------------------------------------
__global__ __launch_bounds__(256)
void resize_kernel(float* __restrict__ out)
{
    const int tid = blockIdx.x * blockDim.x + threadIdx.x;
    if (tid >= BATCH * NP * OH * OW) return;
    const int ow = tid & (OW - 1);
    const int oh = (tid >> 8) & (OH - 1);
    const int c  = tid >> 16;             // c = b*NP + p
    const int b  = c >> 2;
    const int p  = c & 3;
    const int hi = (oh * 3) >> 2;
    const int wi = (ow * 3) >> 2;
    const size_t pix = (size_t)(p * RD + hi) * RH + wi;
    const float4 v = __ldg(&g_xprojP[pix * BATCH + b]);
    out[tid] = (v.x + v.y) + (v.z + v.w);
}

extern "C" void kernel_launch(void* const* d_in, const int* in_sizes, int n_in,
                              void* d_out, int out_size)
{
    const float* x     = (const float*)d_in[0];
    const float* grids = (const float*)d_in[1];
    const float* dx    = (const float*)d_in[2];
    float* out = (float*)d_out;

    const int n_ext = NP * NW * RH + NP * RD * NW + NW;            // 196736
    const int prep_blocks = PACK_BLOCKS + (n_ext + 255) / 256;     // 8192 + 769
    prep_kernel<<<prep_blocks, 256>>>(x, grids);

    proj6_kernel<<<NP * RD * NQ, 192>>>(dx);                       // 3072 blocks

    const int total = BATCH * NP * OH * OW;
    resize_kernel<<<(total + 255) / 256, 256>>>(out);
}

// round 7
// speedup vs baseline: 1.5246x; 1.3257x over previous
#include <cuda_runtime.h>
#include <cuda_fp16.h>
#include <cuda_bf16.h>

// Problem constants
#define VD 128
#define VH 128
#define VW 128
#define VOL (VD*VH*VW)     // 2097152
#define NP 4
#define RD 192
#define RH 192
#define NW 128
#define NPIX (NP*RD*RH)    // 147456 per batch
#define BATCH 2
#define OH 256
#define OW 256
#define NQ 4               // ray quarters
#define WQ (NW/NQ)         // 32 w-steps per block

typedef unsigned long long u64;

// Scratch
// Plaquette: g_plaq[i] = { h2(b0[i],b1[i]), h2(b0[i+1],b1[i+1]),
//                          h2(b0[i+VW],b1[i+VW]), h2(b0[i+VW+1],b1[i+VW+1]) }  (32 MB)
__device__ uint4  g_plaq[VOL];
__device__ float4 g_xprojP[NPIX * BATCH]; // [pix][b] -> 4 quarter partials
__device__ uint4  g_tabEW[NP * NW * RH];  // {e, wx0h2dup, wx1h2dup, 0}, [p][w][rh]
__device__ float  g_tabD [NP * RD * NW];  // c2 table, [p][rd][w]
__device__ float  g_tabH [NW];            // c1 table, [w]

__device__ __forceinline__ int clampi(int v, int lo, int hi) {
    return v < lo ? lo : (v > hi ? hi : v);
}

// ---- f32x2 packed helpers (sm_103a) ----
__device__ __forceinline__ u64 fma2(u64 a, u64 b, u64 c) {
    u64 d; asm("fma.rn.f32x2 %0, %1, %2, %3;" : "=l"(d) : "l"(a), "l"(b), "l"(c)); return d;
}
__device__ __forceinline__ u64 pack2(float lo, float hi) {
    u64 d; asm("mov.b64 %0, {%1, %2};" : "=l"(d) : "f"(lo), "f"(hi)); return d;
}
__device__ __forceinline__ float2 unpack2(u64 v) {
    float lo, hi; asm("mov.b64 {%0, %1}, %2;" : "=f"(lo), "=f"(hi) : "l"(v));
    return make_float2(lo, hi);
}
__device__ __forceinline__ __half2 bith2(unsigned u) {
    return *reinterpret_cast<__half2*>(&u);
}
__device__ __forceinline__ unsigned h2bits(__half2 h) {
    return *reinterpret_cast<unsigned*>(&h);
}
__device__ __forceinline__ u64 h2_to_f32x2(__half2 h) {
    float2 f = __half22float2(h);
    return pack2(f.x, f.y);
}

// ---------------------------------------------------------------------------
// Fused prep:
//  - plaquette pack (blocks 0..8191): per-voxel threads, coalesced 16B stores
//  - tabEW: x-tap index + fp16 dup weights (edge-remapped)
//  - tabD / tabH extraction
// ---------------------------------------------------------------------------
#define PACK_BLOCKS (VOL/256)      // 8192
__global__ __launch_bounds__(256)
void prep_kernel(const float* __restrict__ x, const float* __restrict__ grids)
{
    if (blockIdx.x < PACK_BLOCKS) {
        const int i   = blockIdx.x * 256 + threadIdx.x;
        const int i1  = (i + 1      < VOL) ? i + 1      : VOL - 1;
        const int iw  = (i + VW     < VOL) ? i + VW     : VOL - 1;
        const int iw1 = (i + VW + 1 < VOL) ? i + VW + 1 : VOL - 1;
        const __half2 p00 = __floats2half2_rn(__ldg(&x[i]),   __ldg(&x[i   + VOL]));
        const __half2 p01 = __floats2half2_rn(__ldg(&x[i1]),  __ldg(&x[i1  + VOL]));
        const __half2 p10 = __floats2half2_rn(__ldg(&x[iw]),  __ldg(&x[iw  + VOL]));
        const __half2 p11 = __floats2half2_rn(__ldg(&x[iw1]), __ldg(&x[iw1 + VOL]));
        g_plaq[i] = make_uint4(h2bits(p00), h2bits(p01), h2bits(p10), h2bits(p11));
        return;
    }
    const int tid = (blockIdx.x - PACK_BLOCKS) * 256 + threadIdx.x;
    const int NA = NP * NW * RH;   // 98304
    const int NB = NP * RD * NW;   // 98304
    if (tid < NA) {
        // tid = (p*NW + w)*RH + rh ; c0 read at rd=0 (separable)
        int rh = tid % RH;
        int pw = tid / RH;
        int w  = pw % NW;
        int p  = pw / NW;
        const float c0 = __ldg(&grids[(((size_t)(p * RD + 0) * RH + rh) * NW + w) * 3 + 0]);
        const float ix = (c0 + 1.0f) * (0.5f * (VW - 1));
        const int   x0 = __float2int_rd(ix);
        const float fx = ix - (float)x0;
        const float wx0 = (x0 >= 0  && x0 <= VW - 1) ? (1.0f - fx) : 0.0f;
        const float wx1 = (x0 >= -1 && x0 <= VW - 2) ? fx : 0.0f;
        float w0, w1; int e;
        if (x0 < 0)            { w0 = wx1; w1 = 0.0f; e = 0; }
        else if (x0 > VW - 2)  { w0 = 0.0f; w1 = wx0; e = VW - 2; }
        else                   { w0 = wx0; w1 = wx1; e = x0; }
        g_tabEW[tid] = make_uint4((unsigned)e,
                                  h2bits(__floats2half2_rn(w0, w0)),
                                  h2bits(__floats2half2_rn(w1, w1)), 0u);
    } else if (tid < NA + NB) {
        int t = tid - NA;
        g_tabD[t] = __ldg(&grids[(((size_t)(t / NW) * RH + 0) * NW + (t % NW)) * 3 + 2]);
    } else if (tid < NA + NB + NW) {
        int w = tid - NA - NB;
        g_tabH[w] = __ldg(&grids[(size_t)w * 3 + 1]);
    }
}

// ---------------------------------------------------------------------------
// Projection: block = (p*RD+rd)*NQ + q; 192 threads = rh line; WQ w-steps.
// Per z-tap: ONE LDG.128 fetches the 2x2 (y,x) patch for both batches;
// x/y interp in fp16 (HFMA2), z-fold + accumulation in packed f32x2.
// ---------------------------------------------------------------------------
__global__ __launch_bounds__(192)
void proj7_kernel(const float* __restrict__ dx)
{
    const int bid = blockIdx.x;
    const int q   = bid & (NQ - 1);
    const int blk = bid >> 2;          // p*RD + rd
    const int p   = blk / RD;
    const int rh  = threadIdx.x;
    const int W0  = q * WQ;

    __shared__ int2       s_r [WQ];    // {row base z0, row base z1} (with yb folded)
    __shared__ uint2      s_wy[WQ];    // {wyA dup h2, wyB dup h2}
    __shared__ ulonglong2 s_wz[WQ];    // {wz0 dup f32x2, wz1 dup f32x2}

    if (threadIdx.x < WQ) {
        const int w = W0 + threadIdx.x;
        const float c1 = g_tabH[w];
        const float c2 = g_tabD[blk * NW + w];
        const float iy = (c1 + 1.0f) * (0.5f * (VH - 1));
        const float iz = (c2 + 1.0f) * (0.5f * (VD - 1));
        const float y0f = floorf(iy);
        const float z0f = floorf(iz);
        const float fy = iy - y0f;
        const float fz = iz - z0f;
        const int y0 = (int)y0f;
        const int z0 = (int)z0f;

        // y weights + edge remap onto plaquette rows {yb, yb+1}
        const float wy0 = (y0 >= 0  && y0 <= VH - 1) ? (1.0f - fy) : 0.0f;
        const float wy1 = (y0 >= -1 && y0 <= VH - 2) ? fy : 0.0f;
        float a, b; int yb;
        if (y0 < 0)            { a = wy1; b = 0.0f; yb = 0; }
        else if (y0 > VH - 2)  { a = 0.0f; b = wy0; yb = VH - 2; }
        else                   { a = wy0; b = wy1; yb = y0; }

        // z weights (taps stay separate gathers)
        float wz0 = (z0 >= 0     && z0     <= VD - 1) ? (1.0f - fz) : 0.0f;
        float wz1 = (z0 + 1 >= 0 && z0 + 1 <= VD - 1) ? fz : 0.0f;
        const int zc0 = clampi(z0,     0, VD - 1);
        const int zc1 = clampi(z0 + 1, 0, VD - 1);

        s_r [threadIdx.x] = make_int2((zc0 * VH + yb) * VW, (zc1 * VH + yb) * VW);
        s_wy[threadIdx.x] = make_uint2(h2bits(__floats2half2_rn(a, a)),
                                       h2bits(__floats2half2_rn(b, b)));
        s_wz[threadIdx.x] = make_ulonglong2(pack2(wz0, wz0), pack2(wz1, wz1));
    }
    __syncthreads();

    const uint4* __restrict__ tEW = g_tabEW + (size_t)p * NW * RH + rh;

    u64 acc = 0;   // packed f32x2 {s_batch0, s_batch1}

    #pragma unroll 4
    for (int i = 0; i < WQ; ++i) {
        const int w = W0 + i;
        const uint4 ew = __ldg(&tEW[(size_t)w * RH]);        // coalesced LDG.128
        const int     e    = (int)ew.x;
        const __half2 wx0h = bith2(ew.y);
        const __half2 wx1h = bith2(ew.z);

        const int2       r  = s_r [i];
        const uint2      wy = s_wy[i];
        const ulonglong2 wz = s_wz[i];
        const __half2 wyA = bith2(wy.x);
        const __half2 wyB = bith2(wy.y);

        // z-tap 0
        {
            const uint4 v = __ldg(&g_plaq[r.x + e]);         // 2x2 patch, both batches
            const __half2 t  = __hfma2(bith2(v.y), wx1h, __hmul2(bith2(v.x), wx0h));
            const __half2 u  = __hfma2(bith2(v.w), wx1h, __hmul2(bith2(v.z), wx0h));
            const __half2 pz = __hfma2(u, wyB, __hmul2(t, wyA));
            acc = fma2(wz.x, h2_to_f32x2(pz), acc);
        }
        // z-tap 1
        {
            const uint4 v = __ldg(&g_plaq[r.y + e]);
            const __half2 t  = __hfma2(bith2(v.y), wx1h, __hmul2(bith2(v.x), wx0h));
            const __half2 u  = __hfma2(bith2(v.w), wx1h, __hmul2(bith2(v.z), wx0h));
            const __half2 pz = __hfma2(u, wyB, __hmul2(t, wyA));
            acc = fma2(wz.y, h2_to_f32x2(pz), acc);
        }
    }

    const float2 s = unpack2(acc);
    const int pix = blk * RH + rh;
    const float d = __ldg(&dx[pix]);
    ((float*)&g_xprojP[(size_t)pix * BATCH + 0])[q] = s.x * d;
    ((float*)&g_xprojP[(size_t)pix * BATCH + 1])[q] = s.y * d;
}

// ---------------------------------------------------------------------------
// Nearest resize (192,192)->(256,256), summing the 4 quarter partials.
// ---------------------------------------------------------------------------
__global__ __launch_bounds__(256)
void resize_kernel(float* __restrict__ out)
{
    const int tid = blockIdx.x * blockDim.x + threadIdx.x;
    if (tid >= BATCH * NP * OH * OW) return;
    const int ow = tid & (OW - 1);
    const int oh = (tid >> 8) & (OH - 1);
    const int c  = tid >> 16;             // c = b*NP + p
    const int b  = c >> 2;
    const int p  = c & 3;
    const int hi = (oh * 3) >> 2;
    const int wi = (ow * 3) >> 2;
    const size_t pix = (size_t)(p * RD + hi) * RH + wi;
    const float4 v = __ldg(&g_xprojP[pix * BATCH + b]);
    out[tid] = (v.x + v.y) + (v.z + v.w);
}

extern "C" void kernel_launch(void* const* d_in, const int* in_sizes, int n_in,
                              void* d_out, int out_size)
{
    const float* x     = (const float*)d_in[0];
    const float* grids = (const float*)d_in[1];
    const float* dx    = (const float*)d_in[2];
    float* out = (float*)d_out;

    const int n_ext = NP * NW * RH + NP * RD * NW + NW;            // 196736
    const int prep_blocks = PACK_BLOCKS + (n_ext + 255) / 256;     // 8192 + 769
    prep_kernel<<<prep_blocks, 256>>>(x, grids);

    proj7_kernel<<<NP * RD * NQ, 192>>>(dx);                       // 3072 blocks

    const int total = BATCH * NP * OH * OW;
    resize_kernel<<<(total + 255) / 256, 256>>>(out);
}